// round 11
// baseline (speedup 1.0000x reference)
#include <cuda_runtime.h>
#include <math_constants.h>

#define BATCH 32
#define NROWS 4096
#define HDIM  256
#define H4    (HDIM / 4)          // 64 float4 per row
#define NGRP  512
#define KIDX  16

// scratch: per-(row, channel) max over batch. 4 MB, alloc-free.
__device__ float4 g_bmax[NROWS * H4];

__device__ __forceinline__ void fmax4(float4& m, const float4 v) {
    m.x = fmaxf(m.x, v.x);
    m.y = fmaxf(m.y, v.y);
    m.z = fmaxf(m.z, v.z);
    m.w = fmaxf(m.w, v.w);
}

// Kernel 1: bmax[a][h] = max over 32 batches of x[b,a,h], all rows.
// One thread per (row, float4 chunk): 262144 threads, fully coalesced
// 512B/warp/iter streaming reads. __ldcs = evict-first: read-once stream must
// not evict the bmax table (written below) from L2 before groupmax reads it.
// Unroll 16 + two accumulators -> 16 independent LDG.128 in flight per thread.
__global__ __launch_bounds__(256) void batchmax_kernel(const float4* __restrict__ x) {
    const int i = blockIdx.x * blockDim.x + threadIdx.x;   // 0 .. NROWS*H4-1
    const float4* p = x + i;

    float4 m0 = make_float4(-CUDART_INF_F, -CUDART_INF_F, -CUDART_INF_F, -CUDART_INF_F);
    float4 m1 = m0;
    #pragma unroll 16
    for (int b = 0; b < BATCH; b += 2) {
        const float4 v0 = __ldcs(p + (size_t)(b)     * (NROWS * H4));
        const float4 v1 = __ldcs(p + (size_t)(b + 1) * (NROWS * H4));
        fmax4(m0, v0);
        fmax4(m1, v1);
    }
    fmax4(m0, m1);
    g_bmax[i] = m0;
}

// Kernel 2: out[g][h] = max over the 16 rows idx[g,k] of bmax[row][h].
// One block per group, 256 threads: 4 K-subsets x 64 chunks, smem tree-reduce.
// bmax table (4 MB) is L2-resident thanks to the .cs hints above.
__global__ __launch_bounds__(256) void groupmax_kernel(const int* __restrict__ idx,
                                                       float4* __restrict__ out) {
    const int g   = blockIdx.x;
    const int tid = threadIdx.x;

    __shared__ int sidx[KIDX];
    if (tid < KIDX) sidx[tid] = idx[g * KIDX + tid];
    __syncthreads();

    const int k4 = tid >> 6;         // 0..3 : which 4 indices
    const int c  = tid & 63;         // 0..63: float4 chunk

    float4 m = make_float4(-CUDART_INF_F, -CUDART_INF_F, -CUDART_INF_F, -CUDART_INF_F);
    #pragma unroll
    for (int k = k4 * 4; k < k4 * 4 + 4; ++k)
        fmax4(m, g_bmax[sidx[k] * H4 + c]);

    __shared__ float4 s[256];
    s[tid] = m;
    __syncthreads();

    if (k4 == 0) {
        #pragma unroll
        for (int j = 1; j < 4; ++j)
            fmax4(m, s[j * 64 + c]);
        out[g * H4 + c] = m;
    }
}

extern "C" void kernel_launch(void* const* d_in, const int* in_sizes, int n_in,
                              void* d_out, int out_size) {
    const float4* x = (const float4*)d_in[0];   // (32, 4096*256) fp32
    const int*  idx = (const int*)d_in[1];      // (512, 16) int32
    float4*     out = (float4*)d_out;           // 512*256 fp32 = 2048 float4

    batchmax_kernel<<<(NROWS * H4) / 256, 256>>>(x);
    groupmax_kernel<<<NGRP, 256>>>(idx, out);
    (void)in_sizes; (void)n_in; (void)out_size;
}

// round 12
// speedup vs baseline: 1.0850x; 1.0850x over previous
#include <cuda_runtime.h>
#include <math_constants.h>

#define BATCH 32
#define NROWS 4096
#define HDIM  256
#define H4    (HDIM / 4)          // 64 float4 per row
#define NGRP  512
#define KIDX  16
#define NOUT_IDX (NGRP * KIDX)    // 8192

// scratch: per-(row, channel) max over batch. 4 MB, alloc-free.
__device__ float4 g_bmax[NROWS * H4];
// rows referenced by idx this call (zeroed by groupmax for the next call)
__device__ unsigned char g_mask[NROWS];

__device__ __forceinline__ void fmax4(float4& m, const float4 v) {
    m.x = fmaxf(m.x, v.x);
    m.y = fmaxf(m.y, v.y);
    m.z = fmaxf(m.z, v.z);
    m.w = fmaxf(m.w, v.w);
}

// Kernel 0: flag referenced rows. Benign write races (all write 1).
__global__ __launch_bounds__(256) void set_mask_kernel(const int* __restrict__ idx) {
    const int i = blockIdx.x * blockDim.x + threadIdx.x;
    if (i < NOUT_IDX) g_mask[idx[i]] = 1;
    cudaTriggerProgrammaticLaunchCompletion();
}

// Kernel 1: bmax[a][h] = max over 32 batches of x[b,a,h], flagged rows only
// (~13.5% of rows are never gathered). One thread per (row, float4-chunk),
// fully coalesced streaming reads, batch stride 4 MB. PDL: wait for mask.
__global__ __launch_bounds__(256) void batchmax_kernel(const float4* __restrict__ x) {
    const int i   = blockIdx.x * blockDim.x + threadIdx.x;   // 0 .. NROWS*H4-1
    const int row = i >> 6;

    cudaGridDependencySynchronize();          // mask is ready

    if (g_mask[row]) {
        const float4* p = x + i;
        float4 m = make_float4(-CUDART_INF_F, -CUDART_INF_F, -CUDART_INF_F, -CUDART_INF_F);
        #pragma unroll 8
        for (int b = 0; b < BATCH; ++b)
            fmax4(m, p[(size_t)b * (NROWS * H4)]);
        g_bmax[i] = m;
    }
    cudaTriggerProgrammaticLaunchCompletion(); // after this CTA's stores
}

// Kernel 2: out[g][h] = max over the 16 rows idx[g,k] of bmax[row][h].
// One block per group, 256 threads: 4 K-subsets x 64 chunks, smem tree-reduce.
// Also resets g_mask for the next replay (all batchmax CTAs have triggered,
// i.e. already consumed the mask).
__global__ __launch_bounds__(256) void groupmax_kernel(const int* __restrict__ idx,
                                                       float4* __restrict__ out) {
    const int g   = blockIdx.x;
    const int tid = threadIdx.x;

    cudaGridDependencySynchronize();          // bmax + mask reads are done

    // reset mask for next call (first 16 blocks cover all 4096 rows)
    const int gt = g * 256 + tid;
    if (gt < NROWS) g_mask[gt] = 0;

    __shared__ int sidx[KIDX];
    if (tid < KIDX) sidx[tid] = idx[g * KIDX + tid];
    __syncthreads();

    const int k4 = tid >> 6;         // 0..3 : which 4 indices
    const int c  = tid & 63;         // 0..63: float4 chunk

    float4 m = make_float4(-CUDART_INF_F, -CUDART_INF_F, -CUDART_INF_F, -CUDART_INF_F);
    #pragma unroll
    for (int k = k4 * 4; k < k4 * 4 + 4; ++k)
        fmax4(m, g_bmax[sidx[k] * H4 + c]);

    __shared__ float4 s[256];
    s[tid] = m;
    __syncthreads();

    if (k4 == 0) {
        #pragma unroll
        for (int j = 1; j < 4; ++j)
            fmax4(m, s[j * 64 + c]);
        out[g * H4 + c] = m;
    }
}

static inline void launch_pdl(void* fn, dim3 grid, dim3 block,
                              void** args) {
    cudaLaunchConfig_t cfg = {};
    cfg.gridDim  = grid;
    cfg.blockDim = block;
    cfg.stream   = 0;
    cudaLaunchAttribute attr[1];
    attr[0].id = cudaLaunchAttributeProgrammaticStreamSerialization;
    attr[0].val.programmaticStreamSerializationAllowed = 1;
    cfg.attrs    = attr;
    cfg.numAttrs = 1;
    cudaLaunchKernelExC(&cfg, fn, args);
}

extern "C" void kernel_launch(void* const* d_in, const int* in_sizes, int n_in,
                              void* d_out, int out_size) {
    const float4* x = (const float4*)d_in[0];   // (32, 4096*256) fp32
    const int*  idx = (const int*)d_in[1];      // (512, 16) int32
    float4*     out = (float4*)d_out;           // 512*256 fp32 = 2048 float4

    set_mask_kernel<<<NOUT_IDX / 256, 256>>>(idx);

    {
        void* args[] = { (void*)&x };
        launch_pdl((void*)batchmax_kernel, dim3((NROWS * H4) / 256), dim3(256), args);
    }
    {
        void* args[] = { (void*)&idx, (void*)&out };
        launch_pdl((void*)groupmax_kernel, dim3(NGRP), dim3(256), args);
    }
    (void)in_sizes; (void)n_in; (void)out_size;
}